// round 12
// baseline (speedup 1.0000x reference)
#include <cuda_runtime.h>
#include <cstdint>

// out[n] = S * ( sum_k (x[k]-X_ZP) * y[k,n]  -  Y_ZP * sum_k (x[k]-X_ZP) )
// Exact int32 accumulation. X_SCALE=0.0215, X_ZP=-25, Y_SCALE=0.0176, Y_ZP=18
//
// SINGLE kernel, no split-K across blocks: each of 1024 blocks owns 16
// output columns x the FULL K=8192. Threads: 64 K-slices x 4 threads x int4
// (4 cols). Per row-step a warp reads 8 x 64B contiguous segments (full
// sectors, no overfetch). Block-local 4KB smem combine, direct fp32 output.
// No partial arrays, no second launch, no synchronization constructs.

#define KDIM 8192
#define NDIM 16384
#define THREADS 256
#define KSLICES 64
#define KPER (KDIM / KSLICES)          // 128 rows per thread
#define COLS_PER_BLOCK 16
#define NBLOCKS (NDIM / COLS_PER_BLOCK)  // 1024

__global__ __launch_bounds__(THREADS, 8) void gemv_fullk_kernel(
    const int* __restrict__ x, const int* __restrict__ y,
    float* __restrict__ out)
{
    __shared__ int4 s_red[KSLICES][4];     // per-kslice, per-colgroup partials
    __shared__ int  s_sa[KSLICES];         // per-kslice sum of (x[k]+25)
    __shared__ int  s_sum_a;

    const int tid    = threadIdx.x;
    const int kslice = tid >> 2;           // 0..63
    const int cid    = tid & 3;            // 0..3
    const int col0   = blockIdx.x * COLS_PER_BLOCK + cid * 4;
    const int k0     = kslice * KPER;

    const int4* yp = reinterpret_cast<const int4*>(y + (size_t)k0 * NDIM + col0);
    const int*  xp = x + k0;
    const size_t strideV = NDIM / 4;

    int a0 = 0, a1 = 0, a2 = 0, a3 = 0;
    int sa = 0;
    #pragma unroll 8
    for (int kk = 0; kk < KPER; kk++) {
        const int a = __ldg(&xp[kk]) + 25;     // a[k] = x[k] - X_ZP
        const int4 v = __ldcs(&yp[(size_t)kk * strideV]);
        a0 += a * v.x;  a1 += a * v.y;  a2 += a * v.z;  a3 += a * v.w;
        sa += a;
    }

    s_red[kslice][cid] = make_int4(a0, a1, a2, a3);
    if (cid == 0) s_sa[kslice] = sa;
    __syncthreads();

    // zero-point correction: sum over the 64 kslice sums (one warp)
    if (tid < 32) {
        int s = s_sa[tid] + s_sa[tid + 32];
        #pragma unroll
        for (int o = 16; o > 0; o >>= 1)
            s += __shfl_down_sync(0xffffffffu, s, o);
        if (tid == 0) s_sum_a = s;
    }
    __syncthreads();

    // 16 output columns: col c = component (c&3) of colgroup (c>>2),
    // summed across all 64 kslices.
    if (tid < COLS_PER_BLOCK) {
        const int grp  = tid >> 2;
        const int comp = tid & 3;
        int acc = 0;
        #pragma unroll
        for (int s = 0; s < KSLICES; s++)
            acc += reinterpret_cast<const int*>(&s_red[s][grp])[comp];

        const float S = (float)(0.0215 * 0.0176);
        out[blockIdx.x * COLS_PER_BLOCK + tid] =
            S * (float)(acc - 18 * s_sum_a);
    }
}

extern "C" void kernel_launch(void* const* d_in, const int* in_sizes, int n_in,
                              void* d_out, int out_size) {
    const int* x = (const int*)d_in[0];   // [K]
    const int* y = (const int*)d_in[1];   // [K, N]
    float* out = (float*)d_out;           // [N]

    gemv_fullk_kernel<<<NBLOCKS, THREADS>>>(x, y, out);
}

// round 13
// speedup vs baseline: 2.1071x; 2.1071x over previous
#include <cuda_runtime.h>
#include <cstdint>

// out[n] = S * ( sum_k (x[k]-X_ZP) * y[k,n]  -  Y_ZP * sum_k (x[k]-X_ZP) )
// Exact int32 accumulation. X_SCALE=0.0215, X_ZP=-25, Y_SCALE=0.0176, Y_ZP=18
//
// SINGLE kernel, full-K per block (no split-K, no partials, no 2nd launch).
// 512 blocks x 256 thr; block owns 32 columns x K=8192.
// Threads = 32 kslices x 8 threads x int4: each warp-load touches exactly
// 4 FULL 128B lines (same wavefront cost per byte as the 6.9TB/s R5 layout;
// R12's 172us failure was 8 half-line segments per warp).
// Epilogue: 4KB smem combine, direct fp32 store.

#define KDIM 8192
#define NDIM 16384
#define THREADS 256
#define KSLICES 32
#define KPER (KDIM / KSLICES)            // 256 rows per thread
#define COLS_PER_BLOCK 32                // 8 threads x int4
#define NBLOCKS (NDIM / COLS_PER_BLOCK)  // 512

__global__ __launch_bounds__(THREADS, 4) void gemv_fullk_kernel(
    const int* __restrict__ x, const int* __restrict__ y,
    float* __restrict__ out)
{
    __shared__ int4 s_red[KSLICES][8];   // per-kslice, per-colgroup partials
    __shared__ int  s_sa[KSLICES];       // per-kslice sum of (x[k]+25)
    __shared__ int  s_sum_a;

    const int tid    = threadIdx.x;
    const int kslice = tid >> 3;         // 0..31
    const int cid    = tid & 7;          // 0..7  (8 x 16B = one 128B line)
    const int col0   = blockIdx.x * COLS_PER_BLOCK + cid * 4;
    const int k0     = kslice * KPER;

    const int4* yp = reinterpret_cast<const int4*>(y + (size_t)k0 * NDIM + col0);
    const int*  xp = x + k0;
    const size_t strideV = NDIM / 4;

    int a0 = 0, a1 = 0, a2 = 0, a3 = 0;
    int sa = 0;
    #pragma unroll 8
    for (int kk = 0; kk < KPER; kk++) {
        const int a = __ldg(&xp[kk]) + 25;   // a[k] = x[k] - X_ZP (broadcast)
        const int4 v = __ldcs(&yp[(size_t)kk * strideV]);
        a0 += a * v.x;  a1 += a * v.y;  a2 += a * v.z;  a3 += a * v.w;
        sa += a;
    }

    s_red[kslice][cid] = make_int4(a0, a1, a2, a3);
    if (cid == 0) s_sa[kslice] = sa;
    __syncthreads();

    // zero-point correction: sum of the 32 kslice sums (one warp)
    if (tid < 32) {
        int s = s_sa[tid];
        #pragma unroll
        for (int o = 16; o > 0; o >>= 1)
            s += __shfl_down_sync(0xffffffffu, s, o);
        if (tid == 0) s_sum_a = s;
    }
    __syncthreads();

    // 32 output columns: col c = component (c&3) of colgroup (c>>2),
    // summed across the 32 kslices.
    if (tid < COLS_PER_BLOCK) {
        const int grp  = tid >> 2;
        const int comp = tid & 3;
        int acc = 0;
        #pragma unroll
        for (int s = 0; s < KSLICES; s++)
            acc += reinterpret_cast<const int*>(&s_red[s][grp])[comp];

        const float S = (float)(0.0215 * 0.0176);
        out[blockIdx.x * COLS_PER_BLOCK + tid] =
            S * (float)(acc - 18 * s_sum_a);
    }
}

extern "C" void kernel_launch(void* const* d_in, const int* in_sizes, int n_in,
                              void* d_out, int out_size) {
    const int* x = (const int*)d_in[0];   // [K]
    const int* y = (const int*)d_in[1];   // [K, N]
    float* out = (float*)d_out;           // [N]

    gemv_fullk_kernel<<<NBLOCKS, THREADS>>>(x, y, out);
}